// round 13
// baseline (speedup 1.0000x reference)
#include <cuda_runtime.h>
#include <cuda_fp16.h>
#include <cstdint>

// Problem constants
static constexpr int kB   = 32;      // batch
static constexpr int kHW  = 196;     // 14*14 spatial positions per batch
static constexpr int kC   = 512;     // input channels
static constexpr int kD   = 8192;    // output (hash) dimension, power of two
static constexpr int kNP  = kC * kC; // 262144 (c1,c2) pairs
static constexpr int kKP  = 256;     // K storage stride (zero filled past 196)

// ---------------------------------------------------------------------------
// Scratch (static __device__ arrays; no allocation allowed)
// ---------------------------------------------------------------------------
__device__ __half   g_G [kB * kC * kC];   // G[b][c1][c2] fp16     16 MB
__device__ __half   g_GT[kC * kC * kB];   // GT[c1][c2][b] fp16    16 MB
__device__ __half   g_Ahi[kB * kC * kKP]; // X1 fp16, [b][c][k]     8 MB
__device__ __half   g_Bhi[kB * kC * kKP]; // X2 fp16                8 MB
__device__ int      g_counts [kD];
__device__ int      g_offsets[kD + 1];
__device__ int      g_cursor [kD];
__device__ unsigned g_pairs  [kNP];       // pairIdx (18b) | signbit<<31

__device__ __forceinline__ uint32_t smem_u32(const void* p) {
    uint32_t a;
    asm("{ .reg .u64 t; cvta.to.shared.u64 t, %1; cvt.u32.u64 %0, t; }"
        : "=r"(a) : "l"(p));
    return a;
}

// ---------------------------------------------------------------------------
// Hash/pair-list construction (forked stream)
// ---------------------------------------------------------------------------
__global__ void zero_counts_kernel() {
    int i = blockIdx.x * blockDim.x + threadIdx.x;
    if (i < kD) g_counts[i] = 0;
}

__global__ void hist_kernel(const int* __restrict__ h1, const int* __restrict__ h2) {
    int i = blockIdx.x * blockDim.x + threadIdx.x;
    int c1 = i >> 9, c2 = i & 511;
    int d = (h1[c1] + h2[c2]) & (kD - 1);
    atomicAdd(&g_counts[d], 1);
}

__global__ void scan_kernel() {
    __shared__ int sh[1024];
    int t = threadIdx.x;
    int base = t * 8;
    int v[8];
    int sum = 0;
#pragma unroll
    for (int j = 0; j < 8; j++) { v[j] = g_counts[base + j]; sum += v[j]; }
    sh[t] = sum;
    __syncthreads();
    for (int off = 1; off < 1024; off <<= 1) {
        int x = (t >= off) ? sh[t - off] : 0;
        __syncthreads();
        sh[t] += x;
        __syncthreads();
    }
    int run = sh[t] - sum;
#pragma unroll
    for (int j = 0; j < 8; j++) {
        g_offsets[base + j] = run;
        g_cursor [base + j] = run;
        run += v[j];
    }
    if (t == 1023) g_offsets[kD] = run;
}

__global__ void build_kernel(const float* __restrict__ s1, const float* __restrict__ s2,
                             const int* __restrict__ h1, const int* __restrict__ h2) {
    int i = blockIdx.x * blockDim.x + threadIdx.x;
    int c1 = i >> 9, c2 = i & 511;
    int d = (h1[c1] + h2[c2]) & (kD - 1);
    int pos = atomicAdd(&g_cursor[d], 1);
    unsigned sign = (__float_as_uint(s1[c1]) ^ __float_as_uint(s2[c2])) & 0x80000000u;
    g_pairs[pos] = (unsigned)i | sign;
}

// ---------------------------------------------------------------------------
// Convert + transpose: X[b][k][c] fp32 -> fp16 [b][c][k256], zero-pad K.
// ---------------------------------------------------------------------------
__global__ __launch_bounds__(256) void convert_kernel(const float* __restrict__ x1,
                                                      const float* __restrict__ x2) {
    __shared__ float sh[32][201];
    const int mat = blockIdx.z;        // 0: x1 -> Ahi, 1: x2 -> Bhi
    const int b   = blockIdx.y;
    const int c0  = blockIdx.x * 32;
    const float* X = (mat == 0 ? x1 : x2) + (size_t)b * kHW * kC;
    __half* Hi = (mat == 0 ? g_Ahi : g_Bhi);

    for (int idx = threadIdx.x; idx < kHW * 32; idx += 256) {
        int k = idx >> 5, c = idx & 31;
        sh[c][k] = X[k * kC + c0 + c];
    }
    __syncthreads();
    for (int idx = threadIdx.x; idx < 1024; idx += 256) {
        int c = idx >> 5, k0 = (idx & 31) * 8;
        __half hs[8];
#pragma unroll
        for (int u = 0; u < 8; u++) {
            int k = k0 + u;
            float v = (k < kHW) ? sh[c][k] : 0.0f;
            hs[u] = __float2half_rn(v);
        }
        size_t o = ((size_t)(b * kC + c0 + c) << 8) + k0;
        *(uint4*)&Hi[o] = *(const uint4*)hs;
    }
}

// ---------------------------------------------------------------------------
// HMMA batched GEMM (mma.sync fp16): G[b] = Ahi^T Bhi (single product).
// K = 208; A-chunks {64,64,64,16} = 4 chunks.
// B pre-staged (4 sub-tiles); A double-buffered cp.async.
// CTA tile 128x128, 8 warps, warp tile 32x64. Smem rows 144B.
// Epilogue: stage fp16 tile in smem (272B rows), stream out coalesced.
// ---------------------------------------------------------------------------
static constexpr int kRowB     = 144;                 // 64*2 + 16 pad
static constexpr int kTileB    = 128 * kRowB;         // 18432 per tile
static constexpr int kSmemGemm = 6 * kTileB;          // 110592
static constexpr int kNChunks  = 4;
static constexpr int kEpiRowB  = 272;                 // 256B data + 16B pad

__device__ __forceinline__ void ldsm_x4(uint32_t* r, uint32_t addr) {
    asm volatile("ldmatrix.sync.aligned.m8n8.x4.shared.b16 {%0,%1,%2,%3}, [%4];"
                 : "=r"(r[0]), "=r"(r[1]), "=r"(r[2]), "=r"(r[3]) : "r"(addr));
}
__device__ __forceinline__ void mma_f16(float* d, const uint32_t* a, const uint32_t* b) {
    asm volatile("mma.sync.aligned.m16n8k16.row.col.f32.f16.f16.f32 "
                 "{%0,%1,%2,%3}, {%4,%5,%6,%7}, {%8,%9}, {%0,%1,%2,%3};"
                 : "+f"(d[0]), "+f"(d[1]), "+f"(d[2]), "+f"(d[3])
                 : "r"(a[0]), "r"(a[1]), "r"(a[2]), "r"(a[3]), "r"(b[0]), "r"(b[1]));
}
__device__ __forceinline__ void cp16(uint32_t s, const void* g) {
    asm volatile("cp.async.cg.shared.global [%0], [%1], 16;" :: "r"(s), "l"(g));
}
__device__ __forceinline__ void cp_commit() {
    asm volatile("cp.async.commit_group;" ::: "memory");
}
template <int N>
__device__ __forceinline__ void cp_wait() {
    asm volatile("cp.async.wait_group %0;" :: "n"(N) : "memory");
}

template <int NK>
__device__ __forceinline__ void compute_chunk(uint32_t abase, uint32_t bbase,
                                              int wm, int wn, int g, int r,
                                              float acc[2][8][4]) {
#pragma unroll
    for (int ks = 0; ks < NK; ks++) {
        const int kk = ks * 16;
        uint32_t af[2][4];
#pragma unroll
        for (int mt = 0; mt < 2; mt++) {
            int m = wm + mt * 16 + (g & 1) * 8 + r;
            int kb = (kk + (g >> 1) * 8) * 2;
            ldsm_x4(af[mt], abase + m * kRowB + kb);
        }
        uint32_t bf[8][2];
#pragma unroll
        for (int nt2 = 0; nt2 < 4; nt2++) {
            int n = wn + nt2 * 16 + (g >> 1) * 8 + r;
            int kb = (kk + (g & 1) * 8) * 2;
            uint32_t t4[4];
            ldsm_x4(t4, bbase + n * kRowB + kb);
            bf[2 * nt2][0]     = t4[0]; bf[2 * nt2][1]     = t4[1];
            bf[2 * nt2 + 1][0] = t4[2]; bf[2 * nt2 + 1][1] = t4[3];
        }
#pragma unroll
        for (int mt = 0; mt < 2; mt++)
#pragma unroll
            for (int nt = 0; nt < 8; nt++)
                mma_f16(acc[mt][nt], af[mt], bf[nt]);
    }
}

__global__ __launch_bounds__(256, 2) void mma_kernel() {
    extern __shared__ char dsm[];
    const uint32_t sbase = smem_u32(dsm);

    const int tid  = threadIdx.x;
    const int wid  = tid >> 5, lane = tid & 31;
    const int b      = blockIdx.z;
    const int c1base = blockIdx.y * 128;
    const int c2base = blockIdx.x * 128;
    const int wm = (wid & 3) * 32;
    const int wn = (wid >> 2) * 64;

    float acc[2][8][4];
#pragma unroll
    for (int mt = 0; mt < 2; mt++)
#pragma unroll
        for (int nt = 0; nt < 8; nt++)
#pragma unroll
            for (int q = 0; q < 4; q++) acc[mt][nt][q] = 0.0f;

    const int lrow = tid >> 3;          // 0..31, +32 per j
    const int lseg = tid & 7;

    auto stageA = [&](int ch, int buf) {
        const bool shortC = (ch == 3);
        const __half* Ap = g_Ahi + ((size_t)(b * kC + c1base) << 8) + ch * 64;
        const uint32_t ab = sbase + (4 + buf) * kTileB;
        if (!shortC || lseg < 2) {
#pragma unroll
            for (int j = 0; j < 4; j++) {
                int row = lrow + 32 * j;
                cp16(ab + row * kRowB + lseg * 16, Ap + (size_t)row * kKP + lseg * 8);
            }
        }
        cp_commit();
    };
    auto stageB = [&]() {
#pragma unroll
        for (int sub = 0; sub < 4; sub++) {
            const bool shortC = (sub == 3);
            const __half* Bp = g_Bhi + ((size_t)(b * kC + c2base) << 8) + sub * 64;
            const uint32_t bb = sbase + sub * kTileB;
            if (!shortC || lseg < 2) {
#pragma unroll
                for (int j = 0; j < 4; j++) {
                    int row = lrow + 32 * j;
                    cp16(bb + row * kRowB + lseg * 16, Bp + (size_t)row * kKP + lseg * 8);
                }
            }
        }
    };

    stageB();
    stageA(0, 0);     // group g0 = {B tiles, A0}
    stageA(1, 1);     // group g1 = {A1}
    cp_wait<1>();     // g0 complete
    __syncthreads();

    const int g = lane >> 3, r = lane & 7;

    for (int ch = 0; ch < kNChunks; ch++) {
        const int buf = ch & 1;
        const uint32_t abase = sbase + (4 + buf) * kTileB;
        const uint32_t bbase = sbase + ch * kTileB;
        if (ch == 3)
            compute_chunk<1>(abase, bbase, wm, wn, g, r, acc);
        else
            compute_chunk<4>(abase, bbase, wm, wn, g, r, acc);

        if (ch + 1 < kNChunks) {
            __syncthreads();                 // everyone done reading A[buf]
            if (ch + 2 < kNChunks) {
                stageA(ch + 2, buf);         // refill freed buffer
                cp_wait<1>();                // A[ch+1] complete
            } else {
                cp_wait<0>();
            }
            __syncthreads();                 // visibility of A[ch+1]
        }
    }

    // ---- Epilogue: fp16 tile via smem -> coalesced global stores ----
    __syncthreads();                         // mainloop smem reads done; reuse dsm
    const int er = lane >> 2, ec = (lane & 3) * 2;
#pragma unroll
    for (int mt = 0; mt < 2; mt++) {
#pragma unroll
        for (int nt = 0; nt < 8; nt++) {
            int c2o = wn + nt * 8 + ec;
            int r0  = wm + mt * 16 + er;
            __half2 lo = __float22half2_rn(make_float2(acc[mt][nt][0], acc[mt][nt][1]));
            __half2 hi = __float22half2_rn(make_float2(acc[mt][nt][2], acc[mt][nt][3]));
            *(__half2*)(dsm + r0 * kEpiRowB + c2o * 2)       = lo;
            *(__half2*)(dsm + (r0 + 8) * kEpiRowB + c2o * 2) = hi;
        }
    }
    __syncthreads();
    __half* Gb = g_G + (size_t)b * kC * kC + (size_t)c1base * kC + c2base;
#pragma unroll
    for (int q = 0; q < 8; q++) {
        int idx = tid + 256 * q;             // 0..2047
        int row = idx >> 4, seg = idx & 15;
        uint4 v = *(uint4*)(dsm + row * kEpiRowB + seg * 16);
        *(uint4*)&Gb[(size_t)row * kC + seg * 8] = v;
    }
}

// ---------------------------------------------------------------------------
// Monolithic transpose G[b][c1][c2] -> GT[c1][c2][b], all 32 batches.
// Block (32,32): read rows (b fixed per ty, 64B along c2), write rows
// (c2 fixed per ty, 64B along b). Smem [32][34] halves -> conflict-light.
// ---------------------------------------------------------------------------
__global__ __launch_bounds__(1024) void transpose_kernel() {
    __shared__ __half sh[32][34];
    int c2b = blockIdx.x * 32;
    int tx = threadIdx.x, ty = threadIdx.y;
#pragma unroll
    for (int i = 0; i < 4; i++) {
        int c1 = blockIdx.y * 4 + i;
        // read: b = ty, c2 = c2b + tx (coalesced 64B per b-row)
        sh[ty][tx] = g_G[(size_t)ty * (kC * kC) + c1 * kC + c2b + tx];
        __syncthreads();
        // write: c2 = c2b + ty, b = tx (coalesced 64B per c2-row)
        g_GT[((size_t)c1 * kC + c2b + ty) * kB + tx] = sh[tx][ty];
        __syncthreads();
    }
}

// ---------------------------------------------------------------------------
// Gather (full batch): warp = bucket d; lanes 0-15 pair i, 16-31 pair i+1;
// each lane one __half2 (2 batches). shfl-combine across sides.
// ---------------------------------------------------------------------------
__global__ __launch_bounds__(256) void gather_kernel(float* __restrict__ out) {
    int warp = threadIdx.x >> 5;
    int lane = threadIdx.x & 31;
    int d = blockIdx.x * 8 + warp;
    int i   = g_offsets[d];
    int end = g_offsets[d + 1];
    const int sl   = lane & 15;
    const int side = lane >> 4;

    float ax = 0.0f, ay = 0.0f;
    for (; i + 4 <= end; i += 4) {
        unsigned e0 = g_pairs[i + side];
        unsigned e1 = g_pairs[i + 2 + side];
        unsigned h0 = *(const unsigned*)&g_GT[(size_t)(e0 & 0x7FFFFFFFu) * kB + sl * 2];
        unsigned h1 = *(const unsigned*)&g_GT[(size_t)(e1 & 0x7FFFFFFFu) * kB + sl * 2];
        h0 ^= ((unsigned)((int)e0 >> 31)) & 0x80008000u;
        h1 ^= ((unsigned)((int)e1 >> 31)) & 0x80008000u;
        float2 v0 = __half22float2(*(__half2*)&h0);
        float2 v1 = __half22float2(*(__half2*)&h1);
        ax += v0.x + v1.x;
        ay += v0.y + v1.y;
    }
    if (i + 2 <= end) {
        unsigned e = g_pairs[i + side];
        unsigned h = *(const unsigned*)&g_GT[(size_t)(e & 0x7FFFFFFFu) * kB + sl * 2];
        h ^= ((unsigned)((int)e >> 31)) & 0x80008000u;
        float2 v = __half22float2(*(__half2*)&h);
        ax += v.x;
        ay += v.y;
        i += 2;
    }
    if (i < end && side == 0) {
        unsigned e = g_pairs[i];
        unsigned h = *(const unsigned*)&g_GT[(size_t)(e & 0x7FFFFFFFu) * kB + sl * 2];
        h ^= ((unsigned)((int)e >> 31)) & 0x80008000u;
        float2 v = __half22float2(*(__half2*)&h);
        ax += v.x;
        ay += v.y;
    }

    ax += __shfl_down_sync(0xffffffffu, ax, 16);
    ay += __shfl_down_sync(0xffffffffu, ay, 16);
    if (side == 0) {
        out[(size_t)(2 * sl)     * kD + d] = ax;
        out[(size_t)(2 * sl + 1) * kD + d] = ay;
    }
}

// ---------------------------------------------------------------------------
// Launch. Minimal monolithic graph (8 nodes):
//   s0: C -> M -> T -> [wait setup] -> G
//   sS: zero -> hist -> scan -> build -> evSetup
// ---------------------------------------------------------------------------
extern "C" void kernel_launch(void* const* d_in, const int* in_sizes, int n_in,
                              void* d_out, int out_size) {
    const float* bottom1 = (const float*)d_in[0];
    const float* bottom2 = (const float*)d_in[1];
    const float* rand_s1 = (const float*)d_in[2];
    const float* rand_s2 = (const float*)d_in[3];
    const int*   rand_h1 = (const int*)d_in[4];
    const int*   rand_h2 = (const int*)d_in[5];
    float* out = (float*)d_out;

    cudaFuncSetAttribute(mma_kernel, cudaFuncAttributeMaxDynamicSharedMemorySize,
                         kSmemGemm);

    cudaStreamCaptureStatus st = cudaStreamCaptureStatusNone;
    cudaStreamIsCapturing((cudaStream_t)0, &st);

    const dim3 gConv(kC / 32, kB, 2);
    const dim3 gMma(kC / 128, kC / 128, kB);
    const dim3 gTr(kC / 32, kC / 4);
    const dim3 bTr(32, 32);

    if (st == cudaStreamCaptureStatusActive) {
        cudaStream_t sS;
        cudaStreamCreateWithFlags(&sS, cudaStreamNonBlocking);
        cudaEvent_t evFork, evSetup;
        cudaEventCreateWithFlags(&evFork, cudaEventDisableTiming);
        cudaEventCreateWithFlags(&evSetup, cudaEventDisableTiming);

        cudaEventRecord(evFork, (cudaStream_t)0);
        cudaStreamWaitEvent(sS, evFork, 0);

        // setup branch (hidden under convert+mma)
        zero_counts_kernel<<<8, 1024, 0, sS>>>();
        hist_kernel<<<kNP / 1024, 1024, 0, sS>>>(rand_h1, rand_h2);
        scan_kernel<<<1, 1024, 0, sS>>>();
        build_kernel<<<kNP / 1024, 1024, 0, sS>>>(rand_s1, rand_s2, rand_h1, rand_h2);
        cudaEventRecord(evSetup, sS);

        // main chain
        convert_kernel<<<gConv, 256>>>(bottom1, bottom2);
        mma_kernel<<<gMma, 256, kSmemGemm>>>();
        transpose_kernel<<<gTr, bTr>>>();
        cudaStreamWaitEvent((cudaStream_t)0, evSetup, 0);
        gather_kernel<<<kD / 8, 256>>>(out);

        cudaEventDestroy(evFork);
        cudaEventDestroy(evSetup);
        cudaStreamDestroy(sS);
    } else {
        zero_counts_kernel<<<8, 1024>>>();
        hist_kernel<<<kNP / 1024, 1024>>>(rand_h1, rand_h2);
        scan_kernel<<<1, 1024>>>();
        build_kernel<<<kNP / 1024, 1024>>>(rand_s1, rand_s2, rand_h1, rand_h2);
        convert_kernel<<<gConv, 256>>>(bottom1, bottom2);
        mma_kernel<<<gMma, 256, kSmemGemm>>>();
        transpose_kernel<<<gTr, bTr>>>();
        gather_kernel<<<kD / 8, 256>>>(out);
    }
}

// round 14
// speedup vs baseline: 1.1039x; 1.1039x over previous
#include <cuda_runtime.h>
#include <cuda_fp16.h>
#include <cstdint>

// Problem constants
static constexpr int kB   = 32;      // batch
static constexpr int kHW  = 196;     // 14*14 spatial positions per batch
static constexpr int kC   = 512;     // input channels
static constexpr int kD   = 8192;    // output (hash) dimension, power of two
static constexpr int kNP  = kC * kC; // 262144 (c1,c2) pairs
static constexpr int kKP  = 256;     // K storage stride (zero filled past 196)
static constexpr int kHB  = 16;      // half batch

// ---------------------------------------------------------------------------
// Scratch (static __device__ arrays; no allocation allowed)
// ---------------------------------------------------------------------------
__device__ __half   g_G [kB * kC * kC];   // G[b][c1][c2] fp16     16 MB
__device__ __half   g_GT[kC * kC * kB];   // GT[c1][c2][b] fp16    16 MB
__device__ __half   g_Ahi[kB * kC * kKP]; // X1 fp16, [b][c][k]     8 MB
__device__ __half   g_Bhi[kB * kC * kKP]; // X2 fp16                8 MB
__device__ int      g_counts [kD];
__device__ int      g_offsets[kD + 1];
__device__ int      g_cursor [kD];
__device__ unsigned g_pairs  [kNP];       // pairIdx (18b) | signbit<<31

__device__ __forceinline__ uint32_t smem_u32(const void* p) {
    uint32_t a;
    asm("{ .reg .u64 t; cvta.to.shared.u64 t, %1; cvt.u32.u64 %0, t; }"
        : "=r"(a) : "l"(p));
    return a;
}

// ---------------------------------------------------------------------------
// Hash/pair-list construction (forked stream)
// ---------------------------------------------------------------------------
__global__ void zero_counts_kernel() {
    int i = blockIdx.x * blockDim.x + threadIdx.x;
    if (i < kD) g_counts[i] = 0;
}

__global__ void hist_kernel(const int* __restrict__ h1, const int* __restrict__ h2) {
    int i = blockIdx.x * blockDim.x + threadIdx.x;
    int c1 = i >> 9, c2 = i & 511;
    int d = (h1[c1] + h2[c2]) & (kD - 1);
    atomicAdd(&g_counts[d], 1);
}

__global__ void scan_kernel() {
    __shared__ int sh[1024];
    int t = threadIdx.x;
    int base = t * 8;
    int v[8];
    int sum = 0;
#pragma unroll
    for (int j = 0; j < 8; j++) { v[j] = g_counts[base + j]; sum += v[j]; }
    sh[t] = sum;
    __syncthreads();
    for (int off = 1; off < 1024; off <<= 1) {
        int x = (t >= off) ? sh[t - off] : 0;
        __syncthreads();
        sh[t] += x;
        __syncthreads();
    }
    int run = sh[t] - sum;
#pragma unroll
    for (int j = 0; j < 8; j++) {
        g_offsets[base + j] = run;
        g_cursor [base + j] = run;
        run += v[j];
    }
    if (t == 1023) g_offsets[kD] = run;
}

__global__ void build_kernel(const float* __restrict__ s1, const float* __restrict__ s2,
                             const int* __restrict__ h1, const int* __restrict__ h2) {
    int i = blockIdx.x * blockDim.x + threadIdx.x;
    int c1 = i >> 9, c2 = i & 511;
    int d = (h1[c1] + h2[c2]) & (kD - 1);
    int pos = atomicAdd(&g_cursor[d], 1);
    unsigned sign = (__float_as_uint(s1[c1]) ^ __float_as_uint(s2[c2])) & 0x80000000u;
    g_pairs[pos] = (unsigned)i | sign;
}

// ---------------------------------------------------------------------------
// Convert + transpose: X[b][k][c] fp32 -> fp16 [b][c][k256], zero-pad K.
// ---------------------------------------------------------------------------
__global__ __launch_bounds__(256) void convert_kernel(const float* __restrict__ x1,
                                                      const float* __restrict__ x2,
                                                      int boff) {
    __shared__ float sh[32][201];
    const int mat = blockIdx.z;        // 0: x1 -> Ahi, 1: x2 -> Bhi
    const int b   = boff + blockIdx.y;
    const int c0  = blockIdx.x * 32;
    const float* X = (mat == 0 ? x1 : x2) + (size_t)b * kHW * kC;
    __half* Hi = (mat == 0 ? g_Ahi : g_Bhi);

    for (int idx = threadIdx.x; idx < kHW * 32; idx += 256) {
        int k = idx >> 5, c = idx & 31;
        sh[c][k] = X[k * kC + c0 + c];
    }
    __syncthreads();
    for (int idx = threadIdx.x; idx < 1024; idx += 256) {
        int c = idx >> 5, k0 = (idx & 31) * 8;
        __half hs[8];
#pragma unroll
        for (int u = 0; u < 8; u++) {
            int k = k0 + u;
            float v = (k < kHW) ? sh[c][k] : 0.0f;
            hs[u] = __float2half_rn(v);
        }
        size_t o = ((size_t)(b * kC + c0 + c) << 8) + k0;
        *(uint4*)&Hi[o] = *(const uint4*)hs;
    }
}

// ---------------------------------------------------------------------------
// HMMA batched GEMM (mma.sync fp16): G[b] = Ahi^T Bhi (single product).
// K = 208; A-chunks {64,64,64,16} = 4 chunks.
// Commit groups: g0={B0,A0} g1={B1,A1} g2={B2} g3={B3}; compute starts after
// only g0 (37KB) instead of the whole 110KB. A restages -> g4, g5.
// CTA tile 128x128, 8 warps, warp tile 32x64. Smem rows 144B.
// Epilogue: stage fp16 tile in smem (272B rows), stream out coalesced.
// ---------------------------------------------------------------------------
static constexpr int kRowB     = 144;                 // 64*2 + 16 pad
static constexpr int kTileB    = 128 * kRowB;         // 18432 per tile
static constexpr int kSmemGemm = 6 * kTileB;          // 110592
static constexpr int kEpiRowB  = 272;                 // 256B data + 16B pad

__device__ __forceinline__ void ldsm_x4(uint32_t* r, uint32_t addr) {
    asm volatile("ldmatrix.sync.aligned.m8n8.x4.shared.b16 {%0,%1,%2,%3}, [%4];"
                 : "=r"(r[0]), "=r"(r[1]), "=r"(r[2]), "=r"(r[3]) : "r"(addr));
}
__device__ __forceinline__ void mma_f16(float* d, const uint32_t* a, const uint32_t* b) {
    asm volatile("mma.sync.aligned.m16n8k16.row.col.f32.f16.f16.f32 "
                 "{%0,%1,%2,%3}, {%4,%5,%6,%7}, {%8,%9}, {%0,%1,%2,%3};"
                 : "+f"(d[0]), "+f"(d[1]), "+f"(d[2]), "+f"(d[3])
                 : "r"(a[0]), "r"(a[1]), "r"(a[2]), "r"(a[3]), "r"(b[0]), "r"(b[1]));
}
__device__ __forceinline__ void cp16(uint32_t s, const void* g) {
    asm volatile("cp.async.cg.shared.global [%0], [%1], 16;" :: "r"(s), "l"(g));
}
__device__ __forceinline__ void cp_commit() {
    asm volatile("cp.async.commit_group;" ::: "memory");
}
template <int N>
__device__ __forceinline__ void cp_wait() {
    asm volatile("cp.async.wait_group %0;" :: "n"(N) : "memory");
}

template <int NK>
__device__ __forceinline__ void compute_chunk(uint32_t abase, uint32_t bbase,
                                              int wm, int wn, int g, int r,
                                              float acc[2][8][4]) {
#pragma unroll
    for (int ks = 0; ks < NK; ks++) {
        const int kk = ks * 16;
        uint32_t af[2][4];
#pragma unroll
        for (int mt = 0; mt < 2; mt++) {
            int m = wm + mt * 16 + (g & 1) * 8 + r;
            int kb = (kk + (g >> 1) * 8) * 2;
            ldsm_x4(af[mt], abase + m * kRowB + kb);
        }
        uint32_t bf[8][2];
#pragma unroll
        for (int nt2 = 0; nt2 < 4; nt2++) {
            int n = wn + nt2 * 16 + (g >> 1) * 8 + r;
            int kb = (kk + (g & 1) * 8) * 2;
            uint32_t t4[4];
            ldsm_x4(t4, bbase + n * kRowB + kb);
            bf[2 * nt2][0]     = t4[0]; bf[2 * nt2][1]     = t4[1];
            bf[2 * nt2 + 1][0] = t4[2]; bf[2 * nt2 + 1][1] = t4[3];
        }
#pragma unroll
        for (int mt = 0; mt < 2; mt++)
#pragma unroll
            for (int nt = 0; nt < 8; nt++)
                mma_f16(acc[mt][nt], af[mt], bf[nt]);
    }
}

__global__ __launch_bounds__(256, 2) void mma_kernel(int boff) {
    extern __shared__ char dsm[];
    const uint32_t sbase = smem_u32(dsm);

    const int tid  = threadIdx.x;
    const int wid  = tid >> 5, lane = tid & 31;
    const int b      = boff + blockIdx.z;
    const int c1base = blockIdx.y * 128;
    const int c2base = blockIdx.x * 128;
    const int wm = (wid & 3) * 32;
    const int wn = (wid >> 2) * 64;

    float acc[2][8][4];
#pragma unroll
    for (int mt = 0; mt < 2; mt++)
#pragma unroll
        for (int nt = 0; nt < 8; nt++)
#pragma unroll
            for (int q = 0; q < 4; q++) acc[mt][nt][q] = 0.0f;

    const int lrow = tid >> 3;          // 0..31, +32 per j
    const int lseg = tid & 7;

    // Stage A chunk ch into buffer buf (no commit).
    auto stageA = [&](int ch, int buf) {
        const bool shortC = (ch == 3);
        const __half* Ap = g_Ahi + ((size_t)(b * kC + c1base) << 8) + ch * 64;
        const uint32_t ab = sbase + (4 + buf) * kTileB;
        if (!shortC || lseg < 2) {
#pragma unroll
            for (int j = 0; j < 4; j++) {
                int row = lrow + 32 * j;
                cp16(ab + row * kRowB + lseg * 16, Ap + (size_t)row * kKP + lseg * 8);
            }
        }
    };
    // Stage B sub-tile (no commit).
    auto stageBsub = [&](int sub) {
        const bool shortC = (sub == 3);
        const __half* Bp = g_Bhi + ((size_t)(b * kC + c2base) << 8) + sub * 64;
        const uint32_t bb = sbase + sub * kTileB;
        if (!shortC || lseg < 2) {
#pragma unroll
            for (int j = 0; j < 4; j++) {
                int row = lrow + 32 * j;
                cp16(bb + row * kRowB + lseg * 16, Bp + (size_t)row * kKP + lseg * 8);
            }
        }
    };

    // Prologue commit groups: g0={B0,A0} g1={B1,A1} g2={B2} g3={B3}
    stageBsub(0); stageA(0, 0); cp_commit();
    stageBsub(1); stageA(1, 1); cp_commit();
    stageBsub(2); cp_commit();
    stageBsub(3); cp_commit();

    const int g = lane >> 3, r = lane & 7;

    // chunk 0: need g0 -> all but 3 newest done
    cp_wait<3>();
    __syncthreads();
    compute_chunk<4>(sbase + 4 * kTileB, sbase + 0 * kTileB, wm, wn, g, r, acc);

    // restage A2 into buf0 (g4), then chunk 1 needs g1 -> wait<3> (g2,g3,g4 pend)
    __syncthreads();
    stageA(2, 0); cp_commit();
    cp_wait<3>();
    __syncthreads();
    compute_chunk<4>(sbase + 5 * kTileB, sbase + 1 * kTileB, wm, wn, g, r, acc);

    // restage A3 into buf1 (g5), then chunk 2 needs g2+g4 -> wait<1> (g5 pend)
    __syncthreads();
    stageA(3, 1); cp_commit();
    cp_wait<1>();
    __syncthreads();
    compute_chunk<4>(sbase + 4 * kTileB, sbase + 2 * kTileB, wm, wn, g, r, acc);

    // chunk 3 (short): needs g3+g5 -> wait<0>
    cp_wait<0>();
    __syncthreads();
    compute_chunk<1>(sbase + 5 * kTileB, sbase + 3 * kTileB, wm, wn, g, r, acc);

    // ---- Epilogue: fp16 tile via smem -> coalesced global stores ----
    __syncthreads();                         // mainloop smem reads done; reuse dsm
    const int er = lane >> 2, ec = (lane & 3) * 2;
#pragma unroll
    for (int mt = 0; mt < 2; mt++) {
#pragma unroll
        for (int nt = 0; nt < 8; nt++) {
            int c2o = wn + nt * 8 + ec;
            int r0  = wm + mt * 16 + er;
            __half2 lo = __float22half2_rn(make_float2(acc[mt][nt][0], acc[mt][nt][1]));
            __half2 hi = __float22half2_rn(make_float2(acc[mt][nt][2], acc[mt][nt][3]));
            *(__half2*)(dsm + r0 * kEpiRowB + c2o * 2)       = lo;
            *(__half2*)(dsm + (r0 + 8) * kEpiRowB + c2o * 2) = hi;
        }
    }
    __syncthreads();
    __half* Gb = g_G + (size_t)b * kC * kC + (size_t)c1base * kC + c2base;
#pragma unroll
    for (int q = 0; q < 8; q++) {
        int idx = tid + 256 * q;             // 0..2047
        int row = idx >> 4, seg = idx & 15;
        uint4 v = *(uint4*)(dsm + row * kEpiRowB + seg * 16);
        *(uint4*)&Gb[(size_t)row * kC + seg * 8] = v;
    }
}

// ---------------------------------------------------------------------------
// Transpose G[b][c1][c2] -> GT[c1][c2][b] (fp16) for kHB batches from boff.
// ---------------------------------------------------------------------------
__global__ void transpose_kernel(int boff) {
    __shared__ __half sh[16][36];
    int c2b = blockIdx.x * 32;
    int tx = threadIdx.x, ty = threadIdx.y;
    int wtid = ty * 32 + tx;
    int bb  = wtid & 15;
    int c2o = wtid >> 4;
#pragma unroll
    for (int i = 0; i < 4; i++) {
        int c1 = blockIdx.y * 4 + i;
        sh[ty][tx] = g_G[(size_t)(boff + ty) * (kC * kC) + c1 * kC + c2b + tx];
        __syncthreads();
        g_GT[((size_t)c1 * kC + c2b + c2o) * kB + boff + bb] = sh[bb][c2o];
        __syncthreads();
    }
}

// ---------------------------------------------------------------------------
// Gather (full batch): warp = bucket d; lanes 0-15 pair i, 16-31 pair i+1;
// each lane one __half2 (2 batches). shfl-combine across sides.
// ---------------------------------------------------------------------------
__global__ __launch_bounds__(256) void gather_kernel(float* __restrict__ out) {
    int warp = threadIdx.x >> 5;
    int lane = threadIdx.x & 31;
    int d = blockIdx.x * 8 + warp;
    int i   = g_offsets[d];
    int end = g_offsets[d + 1];
    const int sl   = lane & 15;
    const int side = lane >> 4;

    float ax = 0.0f, ay = 0.0f;
    for (; i + 4 <= end; i += 4) {
        unsigned e0 = g_pairs[i + side];
        unsigned e1 = g_pairs[i + 2 + side];
        unsigned h0 = *(const unsigned*)&g_GT[(size_t)(e0 & 0x7FFFFFFFu) * kB + sl * 2];
        unsigned h1 = *(const unsigned*)&g_GT[(size_t)(e1 & 0x7FFFFFFFu) * kB + sl * 2];
        h0 ^= ((unsigned)((int)e0 >> 31)) & 0x80008000u;
        h1 ^= ((unsigned)((int)e1 >> 31)) & 0x80008000u;
        float2 v0 = __half22float2(*(__half2*)&h0);
        float2 v1 = __half22float2(*(__half2*)&h1);
        ax += v0.x + v1.x;
        ay += v0.y + v1.y;
    }
    if (i + 2 <= end) {
        unsigned e = g_pairs[i + side];
        unsigned h = *(const unsigned*)&g_GT[(size_t)(e & 0x7FFFFFFFu) * kB + sl * 2];
        h ^= ((unsigned)((int)e >> 31)) & 0x80008000u;
        float2 v = __half22float2(*(__half2*)&h);
        ax += v.x;
        ay += v.y;
        i += 2;
    }
    if (i < end && side == 0) {
        unsigned e = g_pairs[i];
        unsigned h = *(const unsigned*)&g_GT[(size_t)(e & 0x7FFFFFFFu) * kB + sl * 2];
        h ^= ((unsigned)((int)e >> 31)) & 0x80008000u;
        float2 v = __half22float2(*(__half2*)&h);
        ax += v.x;
        ay += v.y;
    }

    ax += __shfl_down_sync(0xffffffffu, ax, 16);
    ay += __shfl_down_sync(0xffffffffu, ay, 16);
    if (side == 0) {
        out[(size_t)(2 * sl)     * kD + d] = ax;
        out[(size_t)(2 * sl + 1) * kD + d] = ay;
    }
}

// ---------------------------------------------------------------------------
// Launch. R9 schedule (best measured): two half-chains + setup fork, join
// before a single full gather.
//   s0: C(h0)->M(h0)->T(h0) --\
//   s3: C(h1)->M(h1)->T(h1) ---+--> gather (s0)
//   sS: setup chain ----------/
// ---------------------------------------------------------------------------
extern "C" void kernel_launch(void* const* d_in, const int* in_sizes, int n_in,
                              void* d_out, int out_size) {
    const float* bottom1 = (const float*)d_in[0];
    const float* bottom2 = (const float*)d_in[1];
    const float* rand_s1 = (const float*)d_in[2];
    const float* rand_s2 = (const float*)d_in[3];
    const int*   rand_h1 = (const int*)d_in[4];
    const int*   rand_h2 = (const int*)d_in[5];
    float* out = (float*)d_out;

    cudaFuncSetAttribute(mma_kernel, cudaFuncAttributeMaxDynamicSharedMemorySize,
                         kSmemGemm);

    cudaStreamCaptureStatus st = cudaStreamCaptureStatusNone;
    cudaStreamIsCapturing((cudaStream_t)0, &st);

    const dim3 gConv(kC / 32, kHB, 2);
    const dim3 gMma(kC / 128, kC / 128, kHB);
    const dim3 gTr(kC / 32, kC / 4);
    const dim3 bTr(32, 16);

    if (st == cudaStreamCaptureStatusActive) {
        cudaStream_t s3, sS;
        cudaStreamCreateWithFlags(&s3, cudaStreamNonBlocking);
        cudaStreamCreateWithFlags(&sS, cudaStreamNonBlocking);
        cudaEvent_t evFork, evSetup, evC1;
        cudaEventCreateWithFlags(&evFork, cudaEventDisableTiming);
        cudaEventCreateWithFlags(&evSetup, cudaEventDisableTiming);
        cudaEventCreateWithFlags(&evC1, cudaEventDisableTiming);

        cudaEventRecord(evFork, (cudaStream_t)0);
        cudaStreamWaitEvent(s3, evFork, 0);
        cudaStreamWaitEvent(sS, evFork, 0);

        // setup branch
        zero_counts_kernel<<<8, 1024, 0, sS>>>();
        hist_kernel<<<kNP / 1024, 1024, 0, sS>>>(rand_h1, rand_h2);
        scan_kernel<<<1, 1024, 0, sS>>>();
        build_kernel<<<kNP / 1024, 1024, 0, sS>>>(rand_s1, rand_s2, rand_h1, rand_h2);
        cudaEventRecord(evSetup, sS);

        // half-batch chain 1 (b 16..31)
        convert_kernel<<<gConv, 256, 0, s3>>>(bottom1, bottom2, kHB);
        mma_kernel<<<gMma, 256, kSmemGemm, s3>>>(kHB);
        transpose_kernel<<<gTr, bTr, 0, s3>>>(kHB);
        cudaEventRecord(evC1, s3);

        // half-batch chain 0 (b 0..15) on main stream
        convert_kernel<<<gConv, 256>>>(bottom1, bottom2, 0);
        mma_kernel<<<gMma, 256, kSmemGemm>>>(0);
        transpose_kernel<<<gTr, bTr>>>(0);

        cudaStreamWaitEvent((cudaStream_t)0, evSetup, 0);
        cudaStreamWaitEvent((cudaStream_t)0, evC1, 0);
        gather_kernel<<<kD / 8, 256>>>(out);

        cudaEventDestroy(evFork);
        cudaEventDestroy(evSetup);
        cudaEventDestroy(evC1);
        cudaStreamDestroy(s3);
        cudaStreamDestroy(sS);
    } else {
        zero_counts_kernel<<<8, 1024>>>();
        hist_kernel<<<kNP / 1024, 1024>>>(rand_h1, rand_h2);
        scan_kernel<<<1, 1024>>>();
        build_kernel<<<kNP / 1024, 1024>>>(rand_s1, rand_s2, rand_h1, rand_h2);
        convert_kernel<<<gConv, 256>>>(bottom1, bottom2, 0);
        convert_kernel<<<gConv, 256>>>(bottom1, bottom2, kHB);
        mma_kernel<<<gMma, 256, kSmemGemm>>>(0);
        mma_kernel<<<gMma, 256, kSmemGemm>>>(kHB);
        transpose_kernel<<<gTr, bTr>>>(0);
        transpose_kernel<<<gTr, bTr>>>(kHB);
        gather_kernel<<<kD / 8, 256>>>(out);
    }
}